// round 4
// baseline (speedup 1.0000x reference)
#include <cuda_runtime.h>
#include <math.h>

#define BN_EPS 1e-5f
#define NN_EPS 1e-8f

// Transposed feature scratch: [B=8][N2=4096][C=128]
__device__ float g_ft[8 * 4096 * 128];

// ---------------------------------------------------------------------------
// Kernel A: fused (conv1x1 + BN + ReLU) x2, output transposed to [B, N2, C]
// Tile: M=128 out-channels, N=64 columns. 256 threads, 8x4 micro-tile.
// ---------------------------------------------------------------------------
__global__ __launch_bounds__(256) void fused_mlp_kernel(
    const float* __restrict__ f2,   // [8,256,4096]
    const float* __restrict__ W0,   // [128,256]
    const float* __restrict__ b0, const float* __restrict__ g0,
    const float* __restrict__ be0, const float* __restrict__ m0,
    const float* __restrict__ v0,
    const float* __restrict__ W1,   // [128,128]
    const float* __restrict__ b1, const float* __restrict__ g1,
    const float* __restrict__ be1, const float* __restrict__ m1,
    const float* __restrict__ v1)
{
    __shared__ float As[16][132];   // k x m (transposed weight tile), pad 4
    __shared__ float Bs[16][68];    // k x n input tile, pad 4
    __shared__ float F1[128][68];   // layer-1 output: [k2=128][n=64], pad 4

    const int b  = blockIdx.y;
    const int n0 = blockIdx.x * 64;
    const int t  = threadIdx.x;
    const int tx = t & 15;          // column group: 4 cols
    const int ty = t >> 4;          // row group: 8 rows

    float acc[8][4];
#pragma unroll
    for (int i = 0; i < 8; i++)
#pragma unroll
        for (int j = 0; j < 4; j++) acc[i][j] = 0.f;

    const float* f2b = f2 + ((size_t)b * 256) * 4096 + n0;

    // ---------------- stage 1: C1 = W0 * f2tile, K=256 ----------------
    for (int k0 = 0; k0 < 256; k0 += 16) {
#pragma unroll
        for (int i = 0; i < 2; i++) {
            int idx = t + i * 256;          // float4 index, 512 total
            int m   = idx >> 2;             // 0..127
            int kk4 = (idx & 3) << 2;       // 0,4,8,12
            float4 v = *(const float4*)(W0 + m * 256 + k0 + kk4);
            As[kk4 + 0][m] = v.x; As[kk4 + 1][m] = v.y;
            As[kk4 + 2][m] = v.z; As[kk4 + 3][m] = v.w;
        }
        {
            int kk = t >> 4;                // 0..15
            int n4 = (t & 15) << 2;         // 0..60
            float4 v = *(const float4*)(f2b + (size_t)(k0 + kk) * 4096 + n4);
            *(float4*)&Bs[kk][n4] = v;
        }
        __syncthreads();
#pragma unroll
        for (int kk = 0; kk < 16; kk++) {
            float ra[8], rb[4];
            *(float4*)&ra[0] = *(const float4*)&As[kk][ty * 8];
            *(float4*)&ra[4] = *(const float4*)&As[kk][ty * 8 + 4];
            *(float4*)&rb[0] = *(const float4*)&Bs[kk][tx * 4];
#pragma unroll
            for (int i = 0; i < 8; i++)
#pragma unroll
                for (int j = 0; j < 4; j++)
                    acc[i][j] = fmaf(ra[i], rb[j], acc[i][j]);
        }
        __syncthreads();
    }

    // epilogue 1: BN + ReLU -> F1 smem
#pragma unroll
    for (int i = 0; i < 8; i++) {
        int m = ty * 8 + i;
        float sc = g0[m] * rsqrtf(v0[m] + BN_EPS);
        float bs = be0[m] + (b0[m] - m0[m]) * sc;
#pragma unroll
        for (int j = 0; j < 4; j++) {
            float y = fmaf(acc[i][j], sc, bs);
            F1[m][tx * 4 + j] = fmaxf(y, 0.f);
            acc[i][j] = 0.f;
        }
    }
    __syncthreads();

    // ---------------- stage 2: C2 = W1 * F1, K=128 ----------------
    for (int k0 = 0; k0 < 128; k0 += 16) {
#pragma unroll
        for (int i = 0; i < 2; i++) {
            int idx = t + i * 256;
            int m   = idx >> 2;
            int kk4 = (idx & 3) << 2;
            float4 v = *(const float4*)(W1 + m * 128 + k0 + kk4);
            As[kk4 + 0][m] = v.x; As[kk4 + 1][m] = v.y;
            As[kk4 + 2][m] = v.z; As[kk4 + 3][m] = v.w;
        }
        __syncthreads();
#pragma unroll
        for (int kk = 0; kk < 16; kk++) {
            float ra[8], rb[4];
            *(float4*)&ra[0] = *(const float4*)&As[kk][ty * 8];
            *(float4*)&ra[4] = *(const float4*)&As[kk][ty * 8 + 4];
            *(float4*)&rb[0] = *(const float4*)&F1[k0 + kk][tx * 4];
#pragma unroll
            for (int i = 0; i < 8; i++)
#pragma unroll
                for (int j = 0; j < 4; j++)
                    acc[i][j] = fmaf(ra[i], rb[j], acc[i][j]);
        }
        __syncthreads();
    }

    // epilogue 2: BN + ReLU, write transposed g_ft[b][n][c]
    float sc1[8], bs1[8];
#pragma unroll
    for (int i = 0; i < 8; i++) {
        int m = ty * 8 + i;
        sc1[i] = g1[m] * rsqrtf(v1[m] + BN_EPS);
        bs1[i] = be1[m] + (b1[m] - m1[m]) * sc1[i];
    }
    float* ftb = g_ft + ((size_t)b * 4096 + n0) * 128;
#pragma unroll
    for (int j = 0; j < 4; j++) {
        int n = tx * 4 + j;
        float vals[8];
#pragma unroll
        for (int i = 0; i < 8; i++)
            vals[i] = fmaxf(fmaf(acc[i][j], sc1[i], bs1[i]), 0.f);
        float* dst = ftb + (size_t)n * 128 + ty * 8;
        *(float4*)dst       = *(float4*)&vals[0];
        *(float4*)(dst + 4) = *(float4*)&vals[4];
    }
}

// ---------------------------------------------------------------------------
// Kernel B: 3-NN search + weighted feature interpolation
// One thread per query. p2 staged in SMEM as float4(x,y,z,|p|^2), 2 chunks.
// Rank by partial = |p2|^2 - 2*q.p2 (|q|^2 is per-query constant).
// ---------------------------------------------------------------------------
__global__ __launch_bounds__(256) void interp_kernel(
    const float* __restrict__ p1,   // [8,16384,3]
    const float* __restrict__ p2,   // [8,4096,3]
    float* __restrict__ out)        // [8,128,16384]
{
    __shared__ float4 sp[2048];     // 32 KB

    const int b = blockIdx.y;
    const int t = threadIdx.x;
    const int q = blockIdx.x * 256 + t;

    const float* p1q = p1 + ((size_t)b * 16384 + q) * 3;
    float qx = p1q[0], qy = p1q[1], qz = p1q[2];
    float s1 = qx * qx + qy * qy + qz * qz;
    float ax = -2.f * qx, ay = -2.f * qy, az = -2.f * qz;

    float d0 = 3.4e38f, d1 = 3.4e38f, d2 = 3.4e38f;
    int   i0 = 0, i1 = 0, i2 = 0;

    const float* p2b = p2 + (size_t)b * 4096 * 3;
    for (int c0 = 0; c0 < 4096; c0 += 2048) {
        __syncthreads();
        for (int j = t; j < 2048; j += 256) {
            const float* pp = p2b + (size_t)(c0 + j) * 3;
            float x = pp[0], y = pp[1], z = pp[2];
            sp[j] = make_float4(x, y, z, fmaf(x, x, fmaf(y, y, z * z)));
        }
        __syncthreads();
#pragma unroll 4
        for (int j = 0; j < 2048; j++) {
            float4 P = sp[j];
            float d = fmaf(ax, P.x, fmaf(ay, P.y, fmaf(az, P.z, P.w)));
            if (d < d2) {
                int jj = c0 + j;
                if (d < d1) {
                    d2 = d1; i2 = i1;
                    if (d < d0) { d1 = d0; i1 = i0; d0 = d; i0 = jj; }
                    else        { d1 = d;  i1 = jj; }
                } else { d2 = d; i2 = jj; }
            }
        }
    }

    // actual squared distances and normalized inverse-distance weights
    float D0 = d0 + s1, D1 = d1 + s1, D2 = d2 + s1;
    float r0 = 1.f / (D0 + NN_EPS);
    float r1 = 1.f / (D1 + NN_EPS);
    float r2 = 1.f / (D2 + NN_EPS);
    float inv = 1.f / (r0 + r1 + r2);
    float w0 = r0 * inv, w1 = r1 * inv, w2 = r2 * inv;

    const float4* fA = (const float4*)(g_ft + ((size_t)b * 4096 + i0) * 128);
    const float4* fB = (const float4*)(g_ft + ((size_t)b * 4096 + i1) * 128);
    const float4* fC = (const float4*)(g_ft + ((size_t)b * 4096 + i2) * 128);
    float* ob = out + (size_t)b * 128 * 16384 + q;

#pragma unroll
    for (int cc = 0; cc < 4; cc++) {
        float a[32];
#pragma unroll
        for (int u = 0; u < 8; u++) {
            float4 vA = fA[cc * 8 + u];
            float4 vB = fB[cc * 8 + u];
            float4 vC = fC[cc * 8 + u];
            a[4 * u + 0] = fmaf(w0, vA.x, fmaf(w1, vB.x, w2 * vC.x));
            a[4 * u + 1] = fmaf(w0, vA.y, fmaf(w1, vB.y, w2 * vC.y));
            a[4 * u + 2] = fmaf(w0, vA.z, fmaf(w1, vB.z, w2 * vC.z));
            a[4 * u + 3] = fmaf(w0, vA.w, fmaf(w1, vB.w, w2 * vC.w));
        }
#pragma unroll
        for (int u = 0; u < 32; u++)
            ob[(size_t)(cc * 32 + u) * 16384] = a[u];
    }
}

// ---------------------------------------------------------------------------
extern "C" void kernel_launch(void* const* d_in, const int* in_sizes, int n_in,
                              void* d_out, int out_size) {
    const float* p1  = (const float*)d_in[0];
    const float* p2  = (const float*)d_in[1];
    const float* f2  = (const float*)d_in[2];
    const float* W0  = (const float*)d_in[3];
    const float* b0  = (const float*)d_in[4];
    const float* g0  = (const float*)d_in[5];
    const float* be0 = (const float*)d_in[6];
    const float* m0  = (const float*)d_in[7];
    const float* v0  = (const float*)d_in[8];
    const float* W1  = (const float*)d_in[9];
    const float* b1  = (const float*)d_in[10];
    const float* g1  = (const float*)d_in[11];
    const float* be1 = (const float*)d_in[12];
    const float* m1  = (const float*)d_in[13];
    const float* v1  = (const float*)d_in[14];
    float* out = (float*)d_out;

    dim3 gA(4096 / 64, 8);
    fused_mlp_kernel<<<gA, 256>>>(f2, W0, b0, g0, be0, m0, v0,
                                  W1, b1, g1, be1, m1, v1);

    dim3 gB(16384 / 256, 8);
    interp_kernel<<<gB, 256>>>(p1, p2, out);
}